// round 1
// baseline (speedup 1.0000x reference)
#include <cuda_runtime.h>
#include <math.h>

#define N_LEVELS 16
#define HASHMAP_SIZE 32768
#define HASH_MASK 32767u
#define NPTS 524288

// Materialized per-level tables: [16][32768] x float2  (4 MB, L2-resident)
__device__ float2 g_tables[N_LEVELS * HASHMAP_SIZE];

struct ResParams { float res[N_LEVELS]; };

// ---------------------------------------------------------------------------
// Kernel 1: tables[l][s][:] = A[l][s][0:4] @ B[l][0:4][0:2]
// ---------------------------------------------------------------------------
__global__ void __launch_bounds__(256) build_tables_kernel(
    const float* __restrict__ A, const float* __restrict__ B) {
    int idx = blockIdx.x * blockDim.x + threadIdx.x;   // 0 .. 524287
    int l = idx >> 15;
    float4 a = __ldg(reinterpret_cast<const float4*>(A) + idx);
    const float* b = B + l * 8;                        // [r][f] row-major
    float f0 = a.x * b[0];
    f0 = fmaf(a.y, b[2], f0);
    f0 = fmaf(a.z, b[4], f0);
    f0 = fmaf(a.w, b[6], f0);
    float f1 = a.x * b[1];
    f1 = fmaf(a.y, b[3], f1);
    f1 = fmaf(a.z, b[5], f1);
    f1 = fmaf(a.w, b[7], f1);
    g_tables[idx] = make_float2(f0, f1);
}

// ---------------------------------------------------------------------------
// Kernel 2: hash-grid trilinear encode, one thread per point
// ---------------------------------------------------------------------------
__device__ __forceinline__ float2 lerp2(float2 a, float2 b, float t) {
    return make_float2(fmaf(t, b.x - a.x, a.x),
                       fmaf(t, b.y - a.y, a.y));
}

__global__ void __launch_bounds__(256) encode_kernel(
    const float* __restrict__ x, float* __restrict__ out, ResParams p) {
    int n = blockIdx.x * blockDim.x + threadIdx.x;

    // xn = (x + range) / (2*range), range = 1  -> exact in fp32
    float xn0 = (__ldg(&x[3 * n + 0]) + 1.0f) * 0.5f;
    float xn1 = (__ldg(&x[3 * n + 1]) + 1.0f) * 0.5f;
    float xn2 = (__ldg(&x[3 * n + 2]) + 1.0f) * 0.5f;

    float acc[2 * N_LEVELS];

#pragma unroll
    for (int l = 0; l < N_LEVELS; l++) {
        float r = p.res[l];
        float fx = xn0 * r, fy = xn1 * r, fz = xn2 * r;
        float flx = floorf(fx), fly = floorf(fy), flz = floorf(fz);
        float wx = fx - flx, wy = fy - fly, wz = fz - flz;
        unsigned ix = (unsigned)flx;
        unsigned iy = (unsigned)fly;
        unsigned iz = (unsigned)flz;

        // hash: h = x*1 ^ y*2654435761 ^ z*805459861  (uint32 wraparound)
        unsigned hy0 = iy * 2654435761u;
        unsigned hy1 = hy0 + 2654435761u;
        unsigned hz0 = iz * 805459861u;
        unsigned hz1 = hz0 + 805459861u;
        unsigned x0 = ix, x1 = ix + 1u;

        unsigned b00 = x0 ^ hy0;   // (x,   y  )
        unsigned b10 = x1 ^ hy0;   // (x+1, y  )
        unsigned b01 = x0 ^ hy1;   // (x,   y+1)
        unsigned b11 = x1 ^ hy1;   // (x+1, y+1)

        const float2* tab = g_tables + (l << 15);
        float2 c000 = __ldg(&tab[(b00 ^ hz0) & HASH_MASK]);
        float2 c100 = __ldg(&tab[(b10 ^ hz0) & HASH_MASK]);
        float2 c010 = __ldg(&tab[(b01 ^ hz0) & HASH_MASK]);
        float2 c110 = __ldg(&tab[(b11 ^ hz0) & HASH_MASK]);
        float2 c001 = __ldg(&tab[(b00 ^ hz1) & HASH_MASK]);
        float2 c101 = __ldg(&tab[(b10 ^ hz1) & HASH_MASK]);
        float2 c011 = __ldg(&tab[(b01 ^ hz1) & HASH_MASK]);
        float2 c111 = __ldg(&tab[(b11 ^ hz1) & HASH_MASK]);

        // trilinear via 7 lerps (x, then y, then z)
        float2 m00 = lerp2(c000, c100, wx);
        float2 m10 = lerp2(c010, c110, wx);
        float2 m01 = lerp2(c001, c101, wx);
        float2 m11 = lerp2(c011, c111, wx);
        float2 mm0 = lerp2(m00, m10, wy);
        float2 mm1 = lerp2(m01, m11, wy);
        float2 rr  = lerp2(mm0, mm1, wz);

        acc[2 * l + 0] = rr.x;
        acc[2 * l + 1] = rr.y;
    }

    float4* o = reinterpret_cast<float4*>(out + (size_t)n * 32);
#pragma unroll
    for (int k = 0; k < 8; k++) {
        o[k] = make_float4(acc[4 * k + 0], acc[4 * k + 1],
                           acc[4 * k + 2], acc[4 * k + 3]);
    }
}

// ---------------------------------------------------------------------------
// Launch
// ---------------------------------------------------------------------------
extern "C" void kernel_launch(void* const* d_in, const int* in_sizes, int n_in,
                              void* d_out, int out_size) {
    const float* x = (const float*)d_in[0];        // [524288, 3]
    const float* A = (const float*)d_in[1];        // [16, 32768, 4]
    const float* B = (const float*)d_in[2];        // [16, 4, 2]
    float* out = (float*)d_out;                    // [524288, 32]

    // Replicate numpy's resolution computation bit-exactly (host libm =
    // numpy's scalar path; npy_pow fast-paths for y in {0,1,2}).
    ResParams p;
    double b = exp((log(512.0) - log(16.0)) / 15.0);
    for (int l = 0; l < N_LEVELS; l++) {
        double bl;
        if (l == 0)      bl = 1.0;
        else if (l == 1) bl = b;
        else if (l == 2) bl = b * b;
        else             bl = pow(b, (double)l);
        p.res[l] = (float)floor(16.0 * bl);
    }

    build_tables_kernel<<<(N_LEVELS * HASHMAP_SIZE) / 256, 256>>>(A, B);
    encode_kernel<<<NPTS / 256, 256>>>(x, out, p);
}